// round 12
// baseline (speedup 1.0000x reference)
#include <cuda_runtime.h>
#include <cuda_fp16.h>
#include <cstdint>

#define LATD 256
#define MT 64
#define NJOINT 43
#define BT 6272
#define XDIM 79

// smem: A tile 32KB + B ring 4 x 16KB
#define SMEM_A     0
#define SMEM_BRING 32768
#define SMEM_TOTAL (32768 + 4 * 16384)   // 98304 -> 2 CTAs/SM

// W2 pre-packed in mma.sync B-fragment order:
// g_B[j][s=k16 step 0..15][p=n16 pair 0..15][lane 0..31] : 16B
__device__ unsigned char g_B[(size_t)NJOINT * 16 * 16 * 32 * 16];   // 5.5 MB

// ---------------- helpers ----------------
__device__ __forceinline__ uint32_t smem_u32(const void* p) {
    uint32_t a;
    asm("{ .reg .u64 t; cvta.to.shared.u64 t, %1; cvt.u32.u64 %0, t; }" : "=r"(a) : "l"(p));
    return a;
}
__device__ __forceinline__ void ldsm4(uint32_t* r, uint32_t addr) {
    asm volatile("ldmatrix.sync.aligned.m8n8.x4.shared.b16 {%0,%1,%2,%3}, [%4];"
        : "=r"(r[0]), "=r"(r[1]), "=r"(r[2]), "=r"(r[3]) : "r"(addr));
}
__device__ __forceinline__ void lds128(uint4& v, uint32_t addr) {
    asm volatile("ld.shared.v4.u32 {%0,%1,%2,%3}, [%4];"
        : "=r"(v.x), "=r"(v.y), "=r"(v.z), "=r"(v.w) : "r"(addr));
}
__device__ __forceinline__ void mma_f16(float* d, const uint32_t* a, const uint32_t* b) {
    asm volatile("mma.sync.aligned.m16n8k16.row.col.f32.f16.f16.f32 "
        "{%0,%1,%2,%3}, {%4,%5,%6,%7}, {%8,%9}, {%0,%1,%2,%3};"
        : "+f"(d[0]), "+f"(d[1]), "+f"(d[2]), "+f"(d[3])
        : "r"(a[0]), "r"(a[1]), "r"(a[2]), "r"(a[3]), "r"(b[0]), "r"(b[1]));
}
__device__ __forceinline__ void cp16(uint32_t dst, const void* src) {
    asm volatile("cp.async.cg.shared.global [%0], [%1], 16;" :: "r"(dst), "l"(src) : "memory");
}
#define CP_COMMIT() asm volatile("cp.async.commit_group;" ::: "memory")
#define CP_WAIT(n)  asm volatile("cp.async.wait_group %0;" :: "n"(n) : "memory")

// ---------------- W2 fragment-pack prologue ----------------
__global__ void __launch_bounds__(256)
w2_frag_kernel(const float* __restrict__ W2_3, const float* __restrict__ W2_2,
               const float* __restrict__ W2_1)
{
    __shared__ float ws[32 * 256];
    const int blk = blockIdx.x;
    const int j = blk >> 3, c = blk & 7;
    const float* W2;
    if (j < 13)      W2 = W2_3 + (size_t)j * LATD * LATD;
    else if (j < 23) W2 = W2_2 + (size_t)(j - 13) * LATD * LATD;
    else             W2 = W2_1 + (size_t)(j - 23) * LATD * LATD;

    const int t = threadIdx.x;
    const float4* src4 = (const float4*)(W2 + (size_t)c * 32 * LATD);
    float4* ws4 = (float4*)ws;
    #pragma unroll
    for (int i = 0; i < 8; ++i) ws4[t + i * 256] = src4[t + i * 256];
    __syncthreads();

    unsigned char* dst = g_B + ((size_t)j * 16 + c * 2) * (16 * 32 * 16);
    #pragma unroll
    for (int q = 0; q < 4; ++q) {
        int pid = t + q * 256;
        int lane = pid & 31;
        int p    = (pid >> 5) & 15;
        int ks   = pid >> 9;
        int k0 = ks * 16 + (lane & 3) * 2;
        int n  = p * 16 + (lane >> 2);
        #define PK(kk, nn) ((uint32_t)__half_as_ushort(__float2half_rn(ws[(kk) * 256 + (nn)])))
        uint4 v;
        v.x = PK(k0,     n)     | (PK(k0 + 1, n)     << 16);
        v.y = PK(k0 + 8, n)     | (PK(k0 + 9, n)     << 16);
        v.z = PK(k0,     n + 8) | (PK(k0 + 1, n + 8) << 16);
        v.w = PK(k0 + 8, n + 8) | (PK(k0 + 9, n + 8) << 16);
        #undef PK
        *(uint4*)(dst + (((size_t)ks * 16 + p) * 32 + lane) * 16) = v;
    }
}

// ---------------- main kernel ----------------
__global__ void __launch_bounds__(256, 2)
me_hmma_kernel(const float* __restrict__ x,
               const float* __restrict__ W1_3, const float* __restrict__ b1_3,
               const float* __restrict__ b2_3,
               const float* __restrict__ W1_2, const float* __restrict__ b1_2,
               const float* __restrict__ b2_2,
               const float* __restrict__ W1_1, const float* __restrict__ b1_1,
               const float* __restrict__ b2_1,
               float* __restrict__ out)
{
    extern __shared__ char smem[];
    const uint32_t sb  = smem_u32(smem);
    const uint32_t sbB = sb + SMEM_BRING;
    const int t = threadIdx.x;
    const int lane = t & 31, wid = t >> 5;
    const int j = blockIdx.y;
    const int m0 = blockIdx.x * MT;

    // per-joint meta
    int d, xoff;
    const float *W1, *b1, *b2;
    if (j < 13)      { d = 3; xoff = j * 3;
        W1 = W1_3 + j * 3 * LATD; b1 = b1_3 + j * LATD; b2 = b2_3 + j * LATD; }
    else if (j < 23) { int jj = j - 13; d = 2; xoff = 39 + jj * 2;
        W1 = W1_2 + jj * 2 * LATD; b1 = b1_2 + jj * LATD; b2 = b2_2 + jj * LATD; }
    else             { int jj = j - 23; d = 1; xoff = 59 + jj;
        W1 = W1_1 + jj * LATD;     b1 = b1_1 + jj * LATD; b2 = b2_1 + jj * LATD; }

    const int wm = wid >> 2, wn = wid & 3;
    const uint32_t tOff = (uint32_t)t * 16;

    // per-thread B fragment stream base (step s at +s*512 uint4)
    const uint4* gBw = (const uint4*)(g_B + (size_t)j * 16 * 8192)
                     + (wn * 4) * 32 + lane;

    // ---- issue B stages 0..2 into ring BEFORE phase 1 (overlap) ----
    #pragma unroll
    for (int s = 0; s < 3; ++s) {
        uint32_t dst = sbB + s * 16384 + tOff;
        const uint4* sp = gBw + s * 512;
        #pragma unroll
        for (int nfp = 0; nfp < 4; ++nfp)
            cp16(dst + nfp * 4096, sp + nfp * 32);
        CP_COMMIT();
    }

    // ---- phase 1: H = gelu_tanh(x*W1 + b1) -> swizzled fp16 A tile ----
    {
        const int kbase = lane * 8;
        float w1r[3][8], b1r[8];
        #pragma unroll
        for (int e = 0; e < 8; ++e) b1r[e] = b1[kbase + e];
        #pragma unroll
        for (int i = 0; i < 3; ++i)
            #pragma unroll
            for (int e = 0; e < 8; ++e)
                w1r[i][e] = (i < d) ? W1[i * LATD + kbase + e] : 0.0f;

        #pragma unroll 2
        for (int it = 0; it < 8; ++it) {
            const int m = wid + it * 8;
            const float* xp = x + (size_t)(m0 + m) * XDIM + xoff;
            float x0 = xp[0];
            float x1 = (d > 1) ? xp[1] : 0.0f;
            float x2 = (d > 2) ? xp[2] : 0.0f;
            uint32_t ph[4];
            #pragma unroll
            for (int e2 = 0; e2 < 4; ++e2) {
                unsigned short hh[2];
                #pragma unroll
                for (int e = 0; e < 2; ++e) {
                    const int e8 = e2 * 2 + e;
                    float h = b1r[e8] + x0 * w1r[0][e8] + x1 * w1r[1][e8] + x2 * w1r[2][e8];
                    float cc = 0.7978845608028654f * fmaf(0.044715f * h, h * h, h);
                    float u = 2.8853900817779268f * cc;       // 2c * log2(e)
                    float te; asm("ex2.approx.f32 %0, %1;" : "=f"(te) : "f"(u));
                    float rc; asm("rcp.approx.f32 %0, %1;" : "=f"(rc) : "f"(te + 1.0f));
                    float g = fmaf(-h, rc, h);                // gelu_tanh(h)
                    hh[e] = __half_as_ushort(__float2half_rn(g));
                }
                ph[e2] = hh[0] | ((uint32_t)hh[1] << 16);
            }
            uint32_t addr = (uint32_t)(m * 512) + (uint32_t)((lane ^ (m & 7)) << 4);
            *(uint4*)(smem + SMEM_A + addr) = make_uint4(ph[0], ph[1], ph[2], ph[3]);
        }
    }
    __syncthreads();        // the ONLY barrier: A tile ready for all warps

    // ---- phase 2: fp16 HMMA, warp tile 32x64, B via barrier-free cp.async ring ----
    const int M0 = wm * 32, N0 = wn * 64;
    const uint32_t sw = lane & 7;
    const uint32_t ktop = lane >> 4;                       // 0/1
    const uint32_t rA = (uint32_t)M0 + ((lane >> 3) & 1) * 8 + sw;
    uint32_t aBase[2];
    #pragma unroll
    for (int mf = 0; mf < 2; ++mf) aBase[mf] = sb + (rA + mf * 16) * 512;

    // hoist b2 loads off the epilogue critical path
    const int colb = 2 * (lane & 3);
    float2 b2v[8];
    #pragma unroll
    for (int nf = 0; nf < 8; ++nf)
        b2v[nf] = *(const float2*)(b2 + N0 + nf * 8 + colb);

    float acc[2][8][4];
    #pragma unroll
    for (int mf = 0; mf < 2; ++mf)
        #pragma unroll
        for (int nf = 0; nf < 8; ++nf)
            #pragma unroll
            for (int e = 0; e < 4; ++e) acc[mf][nf][e] = 0.0f;

    #pragma unroll
    for (int s = 0; s < 16; ++s) {
        // issue stage s+3 into the ring slot step s-1 used (private per thread,
        // already consumed by this thread in iter s-1 -> no barrier needed)
        if (s + 3 < 16) {
            uint32_t dst = sbB + ((s + 3) & 3) * 16384 + tOff;
            const uint4* sp = gBw + (s + 3) * 512;
            #pragma unroll
            for (int nfp = 0; nfp < 4; ++nfp)
                cp16(dst + nfp * 4096, sp + nfp * 32);
            CP_COMMIT();
        }
        // wait until stage s has landed
        if (s <= 12)      { CP_WAIT(3); }
        else if (s == 13) { CP_WAIT(2); }
        else if (s == 14) { CP_WAIT(1); }
        else              { CP_WAIT(0); }

        // read this thread's B fragments for step s
        const uint32_t bslot = sbB + (s & 3) * 16384 + tOff;
        uint4 bf[4];
        #pragma unroll
        for (int nfp = 0; nfp < 4; ++nfp)
            lds128(bf[nfp], bslot + nfp * 4096);

        uint32_t ah[2][4];
        const uint32_t koffA = (((uint32_t)(s * 2) + ktop) ^ sw) << 4;
        #pragma unroll
        for (int mf = 0; mf < 2; ++mf)
            ldsm4(ah[mf], aBase[mf] + koffA);

        const uint32_t* b = (const uint32_t*)&bf[0];
        #pragma unroll
        for (int nfp = 0; nfp < 4; ++nfp)
            #pragma unroll
            for (int nn = 0; nn < 2; ++nn)
                #pragma unroll
                for (int mf = 0; mf < 2; ++mf)
                    mma_f16(acc[mf][nfp * 2 + nn], ah[mf], b + nfp * 4 + nn * 2);
    }

    // ---- epilogue: + b2, write out [BT, 43, 256] ----
    {
        #pragma unroll
        for (int mf = 0; mf < 2; ++mf) {
            const int row = M0 + mf * 16 + (lane >> 2);
            float* p0 = out + ((size_t)(m0 + row) * NJOINT + j) * LATD;
            float* p1 = p0 + (size_t)8 * NJOINT * LATD;
            #pragma unroll
            for (int nf = 0; nf < 8; ++nf) {
                const int col = N0 + nf * 8 + colb;
                float2 v0, v1;
                v0.x = acc[mf][nf][0] + b2v[nf].x;
                v0.y = acc[mf][nf][1] + b2v[nf].y;
                v1.x = acc[mf][nf][2] + b2v[nf].x;
                v1.y = acc[mf][nf][3] + b2v[nf].y;
                *(float2*)(p0 + col) = v0;
                *(float2*)(p1 + col) = v1;
            }
        }
    }
}

extern "C" void kernel_launch(void* const* d_in, const int* in_sizes, int n_in,
                              void* d_out, int out_size)
{
    (void)in_sizes; (void)n_in; (void)out_size;
    cudaFuncSetAttribute(me_hmma_kernel,
                         cudaFuncAttributeMaxDynamicSharedMemorySize, SMEM_TOTAL);

    const float* x    = (const float*)d_in[0];
    const float* W1_3 = (const float*)d_in[1];
    const float* b1_3 = (const float*)d_in[2];
    const float* W2_3 = (const float*)d_in[3];
    const float* b2_3 = (const float*)d_in[4];
    const float* W1_2 = (const float*)d_in[5];
    const float* b1_2 = (const float*)d_in[6];
    const float* W2_2 = (const float*)d_in[7];
    const float* b2_2 = (const float*)d_in[8];
    const float* W1_1 = (const float*)d_in[9];
    const float* b1_1 = (const float*)d_in[10];
    const float* W2_1 = (const float*)d_in[11];
    const float* b2_1 = (const float*)d_in[12];

    w2_frag_kernel<<<NJOINT * 8, 256>>>(W2_3, W2_2, W2_1);

    dim3 grid(BT / MT, NJOINT);   // 98 x 43
    me_hmma_kernel<<<grid, 256, SMEM_TOTAL>>>(
        x, W1_3, b1_3, b2_3,
        W1_2, b1_2, b2_2,
        W1_1, b1_1, b2_1,
        (float*)d_out);
}

// round 14
// speedup vs baseline: 1.0569x; 1.0569x over previous
#include <cuda_runtime.h>
#include <cuda_fp16.h>
#include <cstdint>

#define LATD 256
#define MT 64
#define NJOINT 43
#define BT 6272
#define XDIM 79

// smem: A tile only
#define SMEM_TOTAL 32768    // [64 rows][512B] swizzled fp16 H

// W2 pre-packed in mma.sync B-fragment order (unchanged layout):
// g_B[j][s=k16 step 0..15][p=n16 pair 0..15][lane 0..31] : 16B
__device__ unsigned char g_B[(size_t)NJOINT * 16 * 16 * 32 * 16];   // 5.5 MB

// ---------------- helpers ----------------
__device__ __forceinline__ uint32_t smem_u32(const void* p) {
    uint32_t a;
    asm("{ .reg .u64 t; cvta.to.shared.u64 t, %1; cvt.u32.u64 %0, t; }" : "=r"(a) : "l"(p));
    return a;
}
__device__ __forceinline__ void ldsm4(uint32_t* r, uint32_t addr) {
    asm volatile("ldmatrix.sync.aligned.m8n8.x4.shared.b16 {%0,%1,%2,%3}, [%4];"
        : "=r"(r[0]), "=r"(r[1]), "=r"(r[2]), "=r"(r[3]) : "r"(addr));
}
__device__ __forceinline__ void mma_f16(float* d, const uint32_t* a, const uint32_t* b) {
    asm volatile("mma.sync.aligned.m16n8k16.row.col.f32.f16.f16.f32 "
        "{%0,%1,%2,%3}, {%4,%5,%6,%7}, {%8,%9}, {%0,%1,%2,%3};"
        : "+f"(d[0]), "+f"(d[1]), "+f"(d[2]), "+f"(d[3])
        : "r"(a[0]), "r"(a[1]), "r"(a[2]), "r"(a[3]), "r"(b[0]), "r"(b[1]));
}

// ---------------- W2 fragment-pack prologue (identical layout to R10) ----------------
__global__ void __launch_bounds__(256)
w2_frag_kernel(const float* __restrict__ W2_3, const float* __restrict__ W2_2,
               const float* __restrict__ W2_1)
{
    __shared__ float ws[32 * 256];
    const int blk = blockIdx.x;
    const int j = blk >> 3, c = blk & 7;
    const float* W2;
    if (j < 13)      W2 = W2_3 + (size_t)j * LATD * LATD;
    else if (j < 23) W2 = W2_2 + (size_t)(j - 13) * LATD * LATD;
    else             W2 = W2_1 + (size_t)(j - 23) * LATD * LATD;

    const int t = threadIdx.x;
    const float4* src4 = (const float4*)(W2 + (size_t)c * 32 * LATD);
    float4* ws4 = (float4*)ws;
    #pragma unroll
    for (int i = 0; i < 8; ++i) ws4[t + i * 256] = src4[t + i * 256];
    __syncthreads();

    unsigned char* dst = g_B + ((size_t)j * 16 + c * 2) * (16 * 32 * 16);
    #pragma unroll
    for (int q = 0; q < 4; ++q) {
        int pid = t + q * 256;
        int lane = pid & 31;
        int p    = (pid >> 5) & 15;
        int ks   = pid >> 9;
        int k0 = ks * 16 + (lane & 3) * 2;
        int n  = p * 16 + (lane >> 2);
        #define PK(kk, nn) ((uint32_t)__half_as_ushort(__float2half_rn(ws[(kk) * 256 + (nn)])))
        uint4 v;
        v.x = PK(k0,     n)     | (PK(k0 + 1, n)     << 16);
        v.y = PK(k0 + 8, n)     | (PK(k0 + 9, n)     << 16);
        v.z = PK(k0,     n + 8) | (PK(k0 + 1, n + 8) << 16);
        v.w = PK(k0 + 8, n + 8) | (PK(k0 + 9, n + 8) << 16);
        #undef PK
        *(uint4*)(dst + (((size_t)ks * 16 + p) * 32 + lane) * 16) = v;
    }
}

// ---------------- main kernel: 4 warps, warp tile 64x64 ----------------
__global__ void __launch_bounds__(128, 2)
me_hmma_kernel(const float* __restrict__ x,
               const float* __restrict__ W1_3, const float* __restrict__ b1_3,
               const float* __restrict__ b2_3,
               const float* __restrict__ W1_2, const float* __restrict__ b1_2,
               const float* __restrict__ b2_2,
               const float* __restrict__ W1_1, const float* __restrict__ b1_1,
               const float* __restrict__ b2_1,
               float* __restrict__ out)
{
    extern __shared__ char smem[];
    const uint32_t sb = smem_u32(smem);
    const int t = threadIdx.x;
    const int lane = t & 31, wid = t >> 5;          // 4 warps
    const int j = blockIdx.y;
    const int m0 = blockIdx.x * MT;

    // per-joint meta
    int d, xoff;
    const float *W1, *b1, *b2;
    if (j < 13)      { d = 3; xoff = j * 3;
        W1 = W1_3 + j * 3 * LATD; b1 = b1_3 + j * LATD; b2 = b2_3 + j * LATD; }
    else if (j < 23) { int jj = j - 13; d = 2; xoff = 39 + jj * 2;
        W1 = W1_2 + jj * 2 * LATD; b1 = b1_2 + jj * LATD; b2 = b2_2 + jj * LATD; }
    else             { int jj = j - 23; d = 1; xoff = 59 + jj;
        W1 = W1_1 + jj * LATD;     b1 = b1_1 + jj * LATD; b2 = b2_1 + jj * LATD; }

    // per-warp B fragment stream: warp wid owns N0 = wid*64 -> nfp pairs wid*4..wid*4+3
    const uint4* gBw = (const uint4*)(g_B + (size_t)j * 16 * 8192)
                     + (wid * 4) * 32 + lane;

    // B triple-buffer in registers; preload steps 0,1 BEFORE phase-1 (hides L2 latency)
    uint4 bfq[3][4];
    #pragma unroll
    for (int nfp = 0; nfp < 4; ++nfp) bfq[0][nfp] = __ldg(gBw + nfp * 32);
    #pragma unroll
    for (int nfp = 0; nfp < 4; ++nfp) bfq[1][nfp] = __ldg(gBw + 512 + nfp * 32);

    // ---- phase 1: H = gelu_tanh(x*W1 + b1) -> swizzled fp16 A tile (64 rows) ----
    {
        const int kbase = lane * 8;
        float w1r[3][8], b1r[8];
        #pragma unroll
        for (int e = 0; e < 8; ++e) b1r[e] = b1[kbase + e];
        #pragma unroll
        for (int i = 0; i < 3; ++i)
            #pragma unroll
            for (int e = 0; e < 8; ++e)
                w1r[i][e] = (i < d) ? W1[i * LATD + kbase + e] : 0.0f;

        #pragma unroll 4
        for (int it = 0; it < 16; ++it) {
            const int m = wid + it * 4;
            const float* xp = x + (size_t)(m0 + m) * XDIM + xoff;
            float x0 = xp[0];
            float x1 = (d > 1) ? xp[1] : 0.0f;
            float x2 = (d > 2) ? xp[2] : 0.0f;
            uint32_t ph[4];
            #pragma unroll
            for (int e2 = 0; e2 < 4; ++e2) {
                unsigned short hh[2];
                #pragma unroll
                for (int e = 0; e < 2; ++e) {
                    const int e8 = e2 * 2 + e;
                    float h = b1r[e8] + x0 * w1r[0][e8] + x1 * w1r[1][e8] + x2 * w1r[2][e8];
                    float cc = 0.7978845608028654f * fmaf(0.044715f * h, h * h, h);
                    float u = 2.8853900817779268f * cc;       // 2c * log2(e)
                    float te; asm("ex2.approx.f32 %0, %1;" : "=f"(te) : "f"(u));
                    float rc; asm("rcp.approx.f32 %0, %1;" : "=f"(rc) : "f"(te + 1.0f));
                    float g = fmaf(-h, rc, h);                // gelu_tanh(h)
                    hh[e] = __half_as_ushort(__float2half_rn(g));
                }
                ph[e2] = hh[0] | ((uint32_t)hh[1] << 16);
            }
            uint32_t addr = (uint32_t)(m * 512) + (uint32_t)((lane ^ (m & 7)) << 4);
            *(uint4*)(smem + addr) = make_uint4(ph[0], ph[1], ph[2], ph[3]);
        }
    }
    __syncthreads();        // only barrier: A tile ready

    // ---- phase 2: fp16 HMMA, warp tile 64x64 (all warps share M, split N) ----
    const int N0 = wid * 64;
    const uint32_t sw = lane & 7;
    const uint32_t ktop = lane >> 4;                       // 0/1
    const uint32_t rA = ((lane >> 3) & 1) * 8 + sw;        // M0 = 0 for all warps
    uint32_t aBase[4];
    #pragma unroll
    for (int mf = 0; mf < 4; ++mf) aBase[mf] = sb + (rA + mf * 16) * 512;

    // hoist b2 loads
    const int colb = 2 * (lane & 3);
    float2 b2v[8];
    #pragma unroll
    for (int nf = 0; nf < 8; ++nf)
        b2v[nf] = *(const float2*)(b2 + N0 + nf * 8 + colb);

    float acc[4][8][4];
    #pragma unroll
    for (int mf = 0; mf < 4; ++mf)
        #pragma unroll
        for (int nf = 0; nf < 8; ++nf)
            #pragma unroll
            for (int e = 0; e < 4; ++e) acc[mf][nf][e] = 0.0f;

    #pragma unroll
    for (int s = 0; s < 16; ++s) {
        // prefetch step s+2 (distance-2 lookahead)
        if (s + 2 < 16) {
            const uint4* sp = gBw + (s + 2) * 512;
            #pragma unroll
            for (int nfp = 0; nfp < 4; ++nfp)
                bfq[(s + 2) % 3][nfp] = __ldg(sp + nfp * 32);
        }
        uint32_t ah[4][4];
        const uint32_t koffA = (((uint32_t)(s * 2) + ktop) ^ sw) << 4;
        #pragma unroll
        for (int mf = 0; mf < 4; ++mf)
            ldsm4(ah[mf], aBase[mf] + koffA);

        const uint32_t* b = (const uint32_t*)&bfq[s % 3][0];
        #pragma unroll
        for (int nfp = 0; nfp < 4; ++nfp)
            #pragma unroll
            for (int nn = 0; nn < 2; ++nn)
                #pragma unroll
                for (int mf = 0; mf < 4; ++mf)
                    mma_f16(acc[mf][nfp * 2 + nn], ah[mf], b + nfp * 4 + nn * 2);
    }

    // ---- epilogue: + b2, write out [BT, 43, 256] ----
    {
        #pragma unroll
        for (int mf = 0; mf < 4; ++mf) {
            const int row = mf * 16 + (lane >> 2);
            float* p0 = out + ((size_t)(m0 + row) * NJOINT + j) * LATD;
            float* p1 = p0 + (size_t)8 * NJOINT * LATD;
            #pragma unroll
            for (int nf = 0; nf < 8; ++nf) {
                const int col = N0 + nf * 8 + colb;
                float2 v0, v1;
                v0.x = acc[mf][nf][0] + b2v[nf].x;
                v0.y = acc[mf][nf][1] + b2v[nf].y;
                v1.x = acc[mf][nf][2] + b2v[nf].x;
                v1.y = acc[mf][nf][3] + b2v[nf].y;
                *(float2*)(p0 + col) = v0;
                *(float2*)(p1 + col) = v1;
            }
        }
    }
}

extern "C" void kernel_launch(void* const* d_in, const int* in_sizes, int n_in,
                              void* d_out, int out_size)
{
    (void)in_sizes; (void)n_in; (void)out_size;
    cudaFuncSetAttribute(me_hmma_kernel,
                         cudaFuncAttributeMaxDynamicSharedMemorySize, SMEM_TOTAL);

    const float* x    = (const float*)d_in[0];
    const float* W1_3 = (const float*)d_in[1];
    const float* b1_3 = (const float*)d_in[2];
    const float* W2_3 = (const float*)d_in[3];
    const float* b2_3 = (const float*)d_in[4];
    const float* W1_2 = (const float*)d_in[5];
    const float* b1_2 = (const float*)d_in[6];
    const float* W2_2 = (const float*)d_in[7];
    const float* b2_2 = (const float*)d_in[8];
    const float* W1_1 = (const float*)d_in[9];
    const float* b1_1 = (const float*)d_in[10];
    const float* W2_1 = (const float*)d_in[11];
    const float* b2_1 = (const float*)d_in[12];

    w2_frag_kernel<<<NJOINT * 8, 256>>>(W2_3, W2_2, W2_1);

    dim3 grid(BT / MT, NJOINT);   // 98 x 43
    me_hmma_kernel<<<grid, 128, SMEM_TOTAL>>>(
        x, W1_3, b1_3, b2_3,
        W1_2, b1_2, b2_2,
        W1_1, b1_1, b2_1,
        (float*)d_out);
}

// round 16
// speedup vs baseline: 1.0998x; 1.0405x over previous
#include <cuda_runtime.h>
#include <cuda_fp16.h>
#include <cstdint>

#define LATD 256
#define NJOINT 43
#define BT 6272
#define XDIM 79
#define TILES_PER_CTA 7          // 98 m-tiles = 14 groups x 7

// smem: double-buffered A tile
#define SMEM_TOTAL (2 * 32768)   // 64 KB -> 2 CTAs/SM

// W2 pre-packed in mma.sync B-fragment order:
// g_B[j][s=k16 step 0..15][p=n16 pair 0..15][lane 0..31] : 16B
__device__ unsigned char g_B[(size_t)NJOINT * 16 * 16 * 32 * 16];   // 5.5 MB

// ---------------- helpers ----------------
__device__ __forceinline__ uint32_t smem_u32(const void* p) {
    uint32_t a;
    asm("{ .reg .u64 t; cvta.to.shared.u64 t, %1; cvt.u32.u64 %0, t; }" : "=r"(a) : "l"(p));
    return a;
}
__device__ __forceinline__ void ldsm4(uint32_t* r, uint32_t addr) {
    asm volatile("ldmatrix.sync.aligned.m8n8.x4.shared.b16 {%0,%1,%2,%3}, [%4];"
        : "=r"(r[0]), "=r"(r[1]), "=r"(r[2]), "=r"(r[3]) : "r"(addr));
}
__device__ __forceinline__ void mma_f16(float* d, const uint32_t* a, const uint32_t* b) {
    asm volatile("mma.sync.aligned.m16n8k16.row.col.f32.f16.f16.f32 "
        "{%0,%1,%2,%3}, {%4,%5,%6,%7}, {%8,%9}, {%0,%1,%2,%3};"
        : "+f"(d[0]), "+f"(d[1]), "+f"(d[2]), "+f"(d[3])
        : "r"(a[0]), "r"(a[1]), "r"(a[2]), "r"(a[3]), "r"(b[0]), "r"(b[1]));
}

// ---------------- W2 fragment-pack prologue (layout unchanged) ----------------
__global__ void __launch_bounds__(256)
w2_frag_kernel(const float* __restrict__ W2_3, const float* __restrict__ W2_2,
               const float* __restrict__ W2_1)
{
    __shared__ float ws[32 * 256];
    const int blk = blockIdx.x;
    const int j = blk >> 3, c = blk & 7;
    const float* W2;
    if (j < 13)      W2 = W2_3 + (size_t)j * LATD * LATD;
    else if (j < 23) W2 = W2_2 + (size_t)(j - 13) * LATD * LATD;
    else             W2 = W2_1 + (size_t)(j - 23) * LATD * LATD;

    const int t = threadIdx.x;
    const float4* src4 = (const float4*)(W2 + (size_t)c * 32 * LATD);
    float4* ws4 = (float4*)ws;
    #pragma unroll
    for (int i = 0; i < 8; ++i) ws4[t + i * 256] = src4[t + i * 256];
    __syncthreads();

    unsigned char* dst = g_B + ((size_t)j * 16 + c * 2) * (16 * 32 * 16);
    #pragma unroll
    for (int q = 0; q < 4; ++q) {
        int pid = t + q * 256;
        int lane = pid & 31;
        int p    = (pid >> 5) & 15;
        int ks   = pid >> 9;
        int k0 = ks * 16 + (lane & 3) * 2;
        int n  = p * 16 + (lane >> 2);
        #define PK(kk, nn) ((uint32_t)__half_as_ushort(__float2half_rn(ws[(kk) * 256 + (nn)])))
        uint4 v;
        v.x = PK(k0,     n)     | (PK(k0 + 1, n)     << 16);
        v.y = PK(k0 + 8, n)     | (PK(k0 + 9, n)     << 16);
        v.z = PK(k0,     n + 8) | (PK(k0 + 1, n + 8) << 16);
        v.w = PK(k0 + 8, n + 8) | (PK(k0 + 9, n + 8) << 16);
        #undef PK
        *(uint4*)(dst + (((size_t)ks * 16 + p) * 32 + lane) * 16) = v;
    }
}

// phase 1 for one 64-row tile -> swizzled fp16 A at smem buffer
__device__ __forceinline__ void phase1_tile(
    char* bufA, const float* __restrict__ x, int m0t, int wid, int lane,
    const float w1r[3][8], const float b1r[8], int d, int xoff)
{
    #pragma unroll 4
    for (int it = 0; it < 16; ++it) {
        const int m = wid + it * 4;
        const float* xp = x + (size_t)(m0t + m) * XDIM + xoff;
        float x0 = xp[0];
        float x1 = (d > 1) ? xp[1] : 0.0f;
        float x2 = (d > 2) ? xp[2] : 0.0f;
        uint32_t ph[4];
        #pragma unroll
        for (int e2 = 0; e2 < 4; ++e2) {
            unsigned short hh[2];
            #pragma unroll
            for (int e = 0; e < 2; ++e) {
                const int e8 = e2 * 2 + e;
                float h = b1r[e8] + x0 * w1r[0][e8] + x1 * w1r[1][e8] + x2 * w1r[2][e8];
                float cc = 0.7978845608028654f * fmaf(0.044715f * h, h * h, h);
                float u = 2.8853900817779268f * cc;       // 2c * log2(e)
                float te; asm("ex2.approx.f32 %0, %1;" : "=f"(te) : "f"(u));
                float rc; asm("rcp.approx.f32 %0, %1;" : "=f"(rc) : "f"(te + 1.0f));
                float g = fmaf(-h, rc, h);                // gelu_tanh(h)
                hh[e] = __half_as_ushort(__float2half_rn(g));
            }
            ph[e2] = hh[0] | ((uint32_t)hh[1] << 16);
        }
        uint32_t addr = (uint32_t)(m * 512) + (uint32_t)((lane ^ (m & 7)) << 4);
        *(uint4*)(bufA + addr) = make_uint4(ph[0], ph[1], ph[2], ph[3]);
    }
}

// ---------------- main kernel: 4 warps, warp tile 64x64, 7 tiles/CTA ----------------
__global__ void __launch_bounds__(128, 2)
me_hmma_kernel(const float* __restrict__ x,
               const float* __restrict__ W1_3, const float* __restrict__ b1_3,
               const float* __restrict__ b2_3,
               const float* __restrict__ W1_2, const float* __restrict__ b1_2,
               const float* __restrict__ b2_2,
               const float* __restrict__ W1_1, const float* __restrict__ b1_1,
               const float* __restrict__ b2_1,
               float* __restrict__ out)
{
    extern __shared__ char smem[];
    const uint32_t sb = smem_u32(smem);
    const int t = threadIdx.x;
    const int lane = t & 31, wid = t >> 5;          // 4 warps
    const int j = blockIdx.y;
    const int mbase = blockIdx.x * (TILES_PER_CTA * 64);

    // per-joint meta
    int d, xoff;
    const float *W1, *b1, *b2;
    if (j < 13)      { d = 3; xoff = j * 3;
        W1 = W1_3 + j * 3 * LATD; b1 = b1_3 + j * LATD; b2 = b2_3 + j * LATD; }
    else if (j < 23) { int jj = j - 13; d = 2; xoff = 39 + jj * 2;
        W1 = W1_2 + jj * 2 * LATD; b1 = b1_2 + jj * LATD; b2 = b2_2 + jj * LATD; }
    else             { int jj = j - 23; d = 1; xoff = 59 + jj;
        W1 = W1_1 + jj * LATD;     b1 = b1_1 + jj * LATD; b2 = b2_1 + jj * LATD; }

    // per-warp B fragment stream: warp wid owns N0 = wid*64
    const uint4* gBw = (const uint4*)(g_B + (size_t)j * 16 * 8192)
                     + (wid * 4) * 32 + lane;

    // preload B step 0 (L2) — used by first mma step of every tile
    uint4 bfq[2][4];
    #pragma unroll
    for (int nfp = 0; nfp < 4; ++nfp) bfq[0][nfp] = __ldg(gBw + nfp * 32);

    // per-joint layer-1 params in registers (loaded ONCE for all 7 tiles)
    const int kbase = lane * 8;
    float w1r[3][8], b1r[8];
    #pragma unroll
    for (int e = 0; e < 8; ++e) b1r[e] = b1[kbase + e];
    #pragma unroll
    for (int i = 0; i < 3; ++i)
        #pragma unroll
        for (int e = 0; e < 8; ++e)
            w1r[i][e] = (i < d) ? W1[i * LATD + kbase + e] : 0.0f;

    const int N0 = wid * 64;
    const uint32_t swl = lane & 7;
    const uint32_t ktop = lane >> 4;
    const uint32_t rA = ((lane >> 3) & 1) * 8 + swl;
    const int colb = 2 * (lane & 3);
    float2 b2v[8];
    #pragma unroll
    for (int nf = 0; nf < 8; ++nf)
        b2v[nf] = *(const float2*)(b2 + N0 + nf * 8 + colb);

    // phase-1 for tile 0 into buffer 0
    phase1_tile(smem, x, mbase, wid, lane, w1r, b1r, d, xoff);
    __syncthreads();

    float acc[4][8][4];

    #pragma unroll 1
    for (int tt = 0; tt < TILES_PER_CTA; ++tt) {
        const int m0t = mbase + tt * 64;
        const uint32_t bufA = sb + (uint32_t)((tt & 1) * 32768);

        #pragma unroll
        for (int mf = 0; mf < 4; ++mf)
            #pragma unroll
            for (int nf = 0; nf < 8; ++nf)
                #pragma unroll
                for (int e = 0; e < 4; ++e) acc[mf][nf][e] = 0.0f;

        uint32_t aBase[4];
        #pragma unroll
        for (int mf = 0; mf < 4; ++mf) aBase[mf] = bufA + (rA + mf * 16) * 512;

        // ---- MMA over 16 k-steps, B double-buffered (L1/L2-hot after tile 0) ----
        #pragma unroll
        for (int s = 0; s < 16; ++s) {
            if (s + 1 < 16) {
                const uint4* sp = gBw + (s + 1) * 512;
                #pragma unroll
                for (int nfp = 0; nfp < 4; ++nfp)
                    bfq[(s + 1) & 1][nfp] = __ldg(sp + nfp * 32);
            }
            uint32_t ah[4][4];
            const uint32_t koffA = (((uint32_t)(s * 2) + ktop) ^ swl) << 4;
            #pragma unroll
            for (int mf = 0; mf < 4; ++mf)
                ldsm4(ah[mf], aBase[mf] + koffA);

            const uint32_t* b = (const uint32_t*)&bfq[s & 1][0];
            #pragma unroll
            for (int nfp = 0; nfp < 4; ++nfp)
                #pragma unroll
                for (int nn = 0; nn < 2; ++nn)
                    #pragma unroll
                    for (int mf = 0; mf < 4; ++mf)
                        mma_f16(acc[mf][nfp * 2 + nn], ah[mf], b + nfp * 4 + nn * 2);
        }

        // re-arm B step 0 for the next tile (same addresses -> L1 hit)
        if (tt + 1 < TILES_PER_CTA) {
            #pragma unroll
            for (int nfp = 0; nfp < 4; ++nfp) bfq[0][nfp] = __ldg(gBw + nfp * 32);
        }

        // ---- epilogue for tile tt (fire-and-forget stores) ----
        #pragma unroll
        for (int mf = 0; mf < 4; ++mf) {
            const int row = mf * 16 + (lane >> 2);
            float* p0 = out + ((size_t)(m0t + row) * NJOINT + j) * LATD;
            float* p1 = p0 + (size_t)8 * NJOINT * LATD;
            #pragma unroll
            for (int nf = 0; nf < 8; ++nf) {
                const int col = N0 + nf * 8 + colb;
                float2 v0, v1;
                v0.x = acc[mf][nf][0] + b2v[nf].x;
                v0.y = acc[mf][nf][1] + b2v[nf].y;
                v1.x = acc[mf][nf][2] + b2v[nf].x;
                v1.y = acc[mf][nf][3] + b2v[nf].y;
                *(float2*)(p0 + col) = v0;
                *(float2*)(p1 + col) = v1;
            }
        }

        // ---- phase-1 for tile tt+1 into the other buffer (overlaps other warps' MMA) ----
        if (tt + 1 < TILES_PER_CTA)
            phase1_tile(smem + ((tt + 1) & 1) * 32768, x, m0t + 64,
                        wid, lane, w1r, b1r, d, xoff);
        __syncthreads();
    }
}

extern "C" void kernel_launch(void* const* d_in, const int* in_sizes, int n_in,
                              void* d_out, int out_size)
{
    (void)in_sizes; (void)n_in; (void)out_size;
    cudaFuncSetAttribute(me_hmma_kernel,
                         cudaFuncAttributeMaxDynamicSharedMemorySize, SMEM_TOTAL);

    const float* x    = (const float*)d_in[0];
    const float* W1_3 = (const float*)d_in[1];
    const float* b1_3 = (const float*)d_in[2];
    const float* W2_3 = (const float*)d_in[3];
    const float* b2_3 = (const float*)d_in[4];
    const float* W1_2 = (const float*)d_in[5];
    const float* b1_2 = (const float*)d_in[6];
    const float* W2_2 = (const float*)d_in[7];
    const float* b2_2 = (const float*)d_in[8];
    const float* W1_1 = (const float*)d_in[9];
    const float* b1_1 = (const float*)d_in[10];
    const float* W2_1 = (const float*)d_in[11];
    const float* b2_1 = (const float*)d_in[12];

    w2_frag_kernel<<<NJOINT * 8, 256>>>(W2_3, W2_2, W2_1);

    dim3 grid(BT / (TILES_PER_CTA * 64), NJOINT);   // 14 x 43 = 602
    me_hmma_kernel<<<grid, 128, SMEM_TOTAL>>>(
        x, W1_3, b1_3, b2_3,
        W1_2, b1_2, b2_2,
        W1_1, b1_1, b2_1,
        (float*)d_out);
}

// round 17
// speedup vs baseline: 1.2856x; 1.1690x over previous
#include <cuda_runtime.h>
#include <cuda_fp16.h>
#include <cstdint>

#define LATD 256
#define NJOINT 43
#define BT 6272
#define XDIM 79
#define TILES_PER_CTA 7          // 98 m-tiles = 14 groups x 7

// smem: double-buffered A tile
#define SMEM_TOTAL (2 * 32768)   // 64 KB -> 2 CTAs/SM

// W2 pre-packed in mma.sync B-fragment order:
// g_B[j][s=k16 step 0..15][p=n16 pair 0..15][lane 0..31] : 16B
__device__ unsigned char g_B[(size_t)NJOINT * 16 * 16 * 32 * 16];   // 5.5 MB

// ---------------- helpers ----------------
__device__ __forceinline__ uint32_t smem_u32(const void* p) {
    uint32_t a;
    asm("{ .reg .u64 t; cvta.to.shared.u64 t, %1; cvt.u32.u64 %0, t; }" : "=r"(a) : "l"(p));
    return a;
}
__device__ __forceinline__ void ldsm4(uint32_t* r, uint32_t addr) {
    asm volatile("ldmatrix.sync.aligned.m8n8.x4.shared.b16 {%0,%1,%2,%3}, [%4];"
        : "=r"(r[0]), "=r"(r[1]), "=r"(r[2]), "=r"(r[3]) : "r"(addr));
}
__device__ __forceinline__ void mma_f16(float* d, const uint32_t* a, const uint32_t* b) {
    asm volatile("mma.sync.aligned.m16n8k16.row.col.f32.f16.f16.f32 "
        "{%0,%1,%2,%3}, {%4,%5,%6,%7}, {%8,%9}, {%0,%1,%2,%3};"
        : "+f"(d[0]), "+f"(d[1]), "+f"(d[2]), "+f"(d[3])
        : "r"(a[0]), "r"(a[1]), "r"(a[2]), "r"(a[3]), "r"(b[0]), "r"(b[1]));
}

// ---------------- W2 fragment-pack prologue (layout unchanged) ----------------
__global__ void __launch_bounds__(256)
w2_frag_kernel(const float* __restrict__ W2_3, const float* __restrict__ W2_2,
               const float* __restrict__ W2_1)
{
    __shared__ float ws[32 * 256];
    const int blk = blockIdx.x;
    const int j = blk >> 3, c = blk & 7;
    const float* W2;
    if (j < 13)      W2 = W2_3 + (size_t)j * LATD * LATD;
    else if (j < 23) W2 = W2_2 + (size_t)(j - 13) * LATD * LATD;
    else             W2 = W2_1 + (size_t)(j - 23) * LATD * LATD;

    const int t = threadIdx.x;
    const float4* src4 = (const float4*)(W2 + (size_t)c * 32 * LATD);
    float4* ws4 = (float4*)ws;
    #pragma unroll
    for (int i = 0; i < 8; ++i) ws4[t + i * 256] = src4[t + i * 256];
    __syncthreads();

    unsigned char* dst = g_B + ((size_t)j * 16 + c * 2) * (16 * 32 * 16);
    #pragma unroll
    for (int q = 0; q < 4; ++q) {
        int pid = t + q * 256;
        int lane = pid & 31;
        int p    = (pid >> 5) & 15;
        int ks   = pid >> 9;
        int k0 = ks * 16 + (lane & 3) * 2;
        int n  = p * 16 + (lane >> 2);
        #define PK(kk, nn) ((uint32_t)__half_as_ushort(__float2half_rn(ws[(kk) * 256 + (nn)])))
        uint4 v;
        v.x = PK(k0,     n)     | (PK(k0 + 1, n)     << 16);
        v.y = PK(k0 + 8, n)     | (PK(k0 + 9, n)     << 16);
        v.z = PK(k0,     n + 8) | (PK(k0 + 1, n + 8) << 16);
        v.w = PK(k0 + 8, n + 8) | (PK(k0 + 9, n + 8) << 16);
        #undef PK
        *(uint4*)(dst + (((size_t)ks * 16 + p) * 32 + lane) * 16) = v;
    }
}

// phase 1 for one 64-row tile -> swizzled fp16 A; gelu via tanh.approx.f16x2
__device__ __forceinline__ void phase1_tile(
    char* bufA, const float* __restrict__ x, int m0t, int wid, int lane,
    const float w1r[3][8], const float b1r[8], int d, int xoff)
{
    const __half2 one2 = __floats2half2_rn(1.0f, 1.0f);
    #pragma unroll 4
    for (int it = 0; it < 16; ++it) {
        const int m = wid + it * 4;
        const float* xp = x + (size_t)(m0t + m) * XDIM + xoff;
        float x0 = xp[0];
        float x1 = (d > 1) ? xp[1] : 0.0f;
        float x2 = (d > 2) ? xp[2] : 0.0f;
        uint32_t ph[4];
        #pragma unroll
        for (int e2 = 0; e2 < 4; ++e2) {
            float h[2], cc[2];
            #pragma unroll
            for (int e = 0; e < 2; ++e) {
                const int e8 = e2 * 2 + e;
                float hv = fmaf(x2, w1r[2][e8],
                           fmaf(x1, w1r[1][e8],
                           fmaf(x0, w1r[0][e8], b1r[e8])));
                h[e] = hv;
                float hh = hv * hv;
                // cc = 0.79788456*(h + 0.044715 h^3) = h*(C0 + C1*h^2)
                cc[e] = hv * fmaf(0.035677408136300125f, hh, 0.7978845608028654f);
            }
            __half2 cc2 = __floats2half2_rn(cc[0], cc[1]);
            uint32_t t2u;
            asm("tanh.approx.f16x2 %0, %1;"
                : "=r"(t2u) : "r"(*(uint32_t*)&cc2));
            __half2 t2 = *(__half2*)&t2u;
            __half2 h52 = __floats2half2_rn(0.5f * h[0], 0.5f * h[1]);
            __half2 g2 = __hmul2(h52, __hadd2(t2, one2));
            ph[e2] = *(uint32_t*)&g2;
        }
        uint32_t addr = (uint32_t)(m * 512) + (uint32_t)((lane ^ (m & 7)) << 4);
        *(uint4*)(bufA + addr) = make_uint4(ph[0], ph[1], ph[2], ph[3]);
    }
}

// ---------------- main kernel: 4 warps, warp tile 64x64, 7 tiles/CTA ----------------
__global__ void __launch_bounds__(128, 2)
me_hmma_kernel(const float* __restrict__ x,
               const float* __restrict__ W1_3, const float* __restrict__ b1_3,
               const float* __restrict__ b2_3,
               const float* __restrict__ W1_2, const float* __restrict__ b1_2,
               const float* __restrict__ b2_2,
               const float* __restrict__ W1_1, const float* __restrict__ b1_1,
               const float* __restrict__ b2_1,
               float* __restrict__ out)
{
    extern __shared__ char smem[];
    const uint32_t sb = smem_u32(smem);
    const int t = threadIdx.x;
    const int lane = t & 31, wid = t >> 5;          // 4 warps
    const int j = blockIdx.y;
    const int mbase = blockIdx.x * (TILES_PER_CTA * 64);

    // per-joint meta
    int d, xoff;
    const float *W1, *b1, *b2;
    if (j < 13)      { d = 3; xoff = j * 3;
        W1 = W1_3 + j * 3 * LATD; b1 = b1_3 + j * LATD; b2 = b2_3 + j * LATD; }
    else if (j < 23) { int jj = j - 13; d = 2; xoff = 39 + jj * 2;
        W1 = W1_2 + jj * 2 * LATD; b1 = b1_2 + jj * LATD; b2 = b2_2 + jj * LATD; }
    else             { int jj = j - 23; d = 1; xoff = 59 + jj;
        W1 = W1_1 + jj * LATD;     b1 = b1_1 + jj * LATD; b2 = b2_1 + jj * LATD; }

    // per-warp B fragment stream: warp wid owns N0 = wid*64
    const uint4* gBw = (const uint4*)(g_B + (size_t)j * 16 * 8192)
                     + (wid * 4) * 32 + lane;

    // preload B step 0 (L2) — used by first mma step of every tile
    uint4 bfq[2][4];
    #pragma unroll
    for (int nfp = 0; nfp < 4; ++nfp) bfq[0][nfp] = __ldg(gBw + nfp * 32);

    // per-joint layer-1 params in registers (loaded ONCE for all 7 tiles)
    const int kbase = lane * 8;
    float w1r[3][8], b1r[8];
    #pragma unroll
    for (int e = 0; e < 8; ++e) b1r[e] = b1[kbase + e];
    #pragma unroll
    for (int i = 0; i < 3; ++i)
        #pragma unroll
        for (int e = 0; e < 8; ++e)
            w1r[i][e] = (i < d) ? W1[i * LATD + kbase + e] : 0.0f;

    const int N0 = wid * 64;
    const uint32_t swl = lane & 7;
    const uint32_t ktop = lane >> 4;
    const uint32_t rA = ((lane >> 3) & 1) * 8 + swl;
    const int colb = 2 * (lane & 3);
    float2 b2v[8];
    #pragma unroll
    for (int nf = 0; nf < 8; ++nf)
        b2v[nf] = *(const float2*)(b2 + N0 + nf * 8 + colb);

    // phase-1 for tile 0 into buffer 0
    phase1_tile(smem, x, mbase, wid, lane, w1r, b1r, d, xoff);
    __syncthreads();

    float acc[4][8][4];

    #pragma unroll 1
    for (int tt = 0; tt < TILES_PER_CTA; ++tt) {
        const int m0t = mbase + tt * 64;
        const uint32_t bufA = sb + (uint32_t)((tt & 1) * 32768);

        #pragma unroll
        for (int mf = 0; mf < 4; ++mf)
            #pragma unroll
            for (int nf = 0; nf < 8; ++nf)
                #pragma unroll
                for (int e = 0; e < 4; ++e) acc[mf][nf][e] = 0.0f;

        uint32_t aBase[4];
        #pragma unroll
        for (int mf = 0; mf < 4; ++mf) aBase[mf] = bufA + (rA + mf * 16) * 512;

        // ---- MMA over 16 k-steps, B double-buffered (L1/L2-hot after tile 0) ----
        #pragma unroll
        for (int s = 0; s < 16; ++s) {
            if (s + 1 < 16) {
                const uint4* sp = gBw + (s + 1) * 512;
                #pragma unroll
                for (int nfp = 0; nfp < 4; ++nfp)
                    bfq[(s + 1) & 1][nfp] = __ldg(sp + nfp * 32);
            }
            uint32_t ah[4][4];
            const uint32_t koffA = (((uint32_t)(s * 2) + ktop) ^ swl) << 4;
            #pragma unroll
            for (int mf = 0; mf < 4; ++mf)
                ldsm4(ah[mf], aBase[mf] + koffA);

            const uint32_t* b = (const uint32_t*)&bfq[s & 1][0];
            #pragma unroll
            for (int nfp = 0; nfp < 4; ++nfp)
                #pragma unroll
                for (int nn = 0; nn < 2; ++nn)
                    #pragma unroll
                    for (int mf = 0; mf < 4; ++mf)
                        mma_f16(acc[mf][nfp * 2 + nn], ah[mf], b + nfp * 4 + nn * 2);
        }

        // re-arm B step 0 for the next tile (same addresses -> L1 hit)
        if (tt + 1 < TILES_PER_CTA) {
            #pragma unroll
            for (int nfp = 0; nfp < 4; ++nfp) bfq[0][nfp] = __ldg(gBw + nfp * 32);
        }

        // ---- epilogue for tile tt (fire-and-forget stores) ----
        #pragma unroll
        for (int mf = 0; mf < 4; ++mf) {
            const int row = mf * 16 + (lane >> 2);
            float* p0 = out + ((size_t)(m0t + row) * NJOINT + j) * LATD;
            float* p1 = p0 + (size_t)8 * NJOINT * LATD;
            #pragma unroll
            for (int nf = 0; nf < 8; ++nf) {
                const int col = N0 + nf * 8 + colb;
                float2 v0, v1;
                v0.x = acc[mf][nf][0] + b2v[nf].x;
                v0.y = acc[mf][nf][1] + b2v[nf].y;
                v1.x = acc[mf][nf][2] + b2v[nf].x;
                v1.y = acc[mf][nf][3] + b2v[nf].y;
                *(float2*)(p0 + col) = v0;
                *(float2*)(p1 + col) = v1;
            }
        }

        // ---- phase-1 for tile tt+1 into the other buffer (overlaps other warps' MMA) ----
        if (tt + 1 < TILES_PER_CTA)
            phase1_tile(smem + ((tt + 1) & 1) * 32768, x, m0t + 64,
                        wid, lane, w1r, b1r, d, xoff);
        __syncthreads();
    }
}

extern "C" void kernel_launch(void* const* d_in, const int* in_sizes, int n_in,
                              void* d_out, int out_size)
{
    (void)in_sizes; (void)n_in; (void)out_size;
    cudaFuncSetAttribute(me_hmma_kernel,
                         cudaFuncAttributeMaxDynamicSharedMemorySize, SMEM_TOTAL);

    const float* x    = (const float*)d_in[0];
    const float* W1_3 = (const float*)d_in[1];
    const float* b1_3 = (const float*)d_in[2];
    const float* W2_3 = (const float*)d_in[3];
    const float* b2_3 = (const float*)d_in[4];
    const float* W1_2 = (const float*)d_in[5];
    const float* b1_2 = (const float*)d_in[6];
    const float* W2_2 = (const float*)d_in[7];
    const float* b2_2 = (const float*)d_in[8];
    const float* W1_1 = (const float*)d_in[9];
    const float* b1_1 = (const float*)d_in[10];
    const float* W2_1 = (const float*)d_in[11];
    const float* b2_1 = (const float*)d_in[12];

    w2_frag_kernel<<<NJOINT * 8, 256>>>(W2_3, W2_2, W2_1);

    dim3 grid(BT / (TILES_PER_CTA * 64), NJOINT);   // 14 x 43 = 602
    me_hmma_kernel<<<grid, 128, SMEM_TOTAL>>>(
        x, W1_3, b1_3, b2_3,
        W1_2, b1_2, b2_2,
        W1_1, b1_1, b2_1,
        (float*)d_out);
}